// round 9
// baseline (speedup 1.0000x reference)
#include <cuda_runtime.h>
#include <math.h>

#define NN   50000
#define EE   800000
#define ET   (EE + NN)        // edges + self loops
#define FIN  128
#define HID  64
#define NEG_SLOPE 0.2f

#define SCAN_B   256
#define SCAN_G   ((NN + SCAN_B - 1) / SCAN_B)   // 196
#define NWARPS   (SCAN_B / 32)                  // 8

#define GR   128              // gemm rows per block
#define KCH  32               // gemm k-chunk per phase
#define XPAD 4                // row padding for transpose store

struct __align__(8) EW { int s; float w; };

// ---------------- scratch (device globals; no allocs allowed) ----------------
__device__ float g_h[NN * HID];        // x @ W
__device__ float g_asrc[NN];
__device__ float g_adst[NN];
__device__ int   g_count[NN];          // degree histogram
__device__ int   g_cursor[NN];         // scatter cursors
__device__ int   g_offsets[NN + 1];    // CSR offsets
__device__ EW    g_ew[ET];             // (src, weight) per CSR slot
__device__ int2  g_sd[EE];             // packed (src,dst) int32
__device__ float g_we[EE];             // per-edge exp(leaky(e)), edge order
__device__ float g_s0[NN];
__device__ float g_s1[NN];
__device__ int   g_bsum[SCAN_G];       // per-block count sums
__device__ int   g_is64;

__device__ __forceinline__ int edge_at(const void* p, long long i, int is64) {
    return is64 ? (int)((const long long*)p)[i] : ((const int*)p)[i];
}

// packed fp32x2 helpers (Blackwell)
__device__ __forceinline__ unsigned long long fma2(unsigned long long a,
                                                   unsigned long long b,
                                                   unsigned long long c) {
    unsigned long long d;
    asm("fma.rn.f32x2 %0, %1, %2, %3;" : "=l"(d) : "l"(a), "l"(b), "l"(c));
    return d;
}
__device__ __forceinline__ unsigned long long pack2(float lo, float hi) {
    unsigned long long r;
    asm("mov.b64 %0, {%1, %2};" : "=l"(r) : "f"(lo), "f"(hi));
    return r;
}
__device__ __forceinline__ float2 unpack2(unsigned long long v) {
    float2 r;
    asm("mov.b64 {%0, %1}, %2;" : "=f"(r.x), "=f"(r.y) : "l"(v));
    return r;
}

__device__ __forceinline__ float leaky_exp(float e) {
    e = (e > 0.f) ? e : NEG_SLOPE * e;
    return __expf(e);
}

// ---------------- init: counts=1 (self-loop pre-counted) + dtype detect ----
__global__ void init_kernel(const int* ew) {
    int i = blockIdx.x * blockDim.x + threadIdx.x;
    if (i < NN) g_count[i] = 1;          // self loop contributes 1 per node
    if (i == 0) {
        int all0 = 1;
        #pragma unroll 8
        for (int j = 0; j < 64; j++) {
            if (ew[2 * j + 1] != 0) { all0 = 0; break; }
        }
        g_is64 = all0;
    }
}

// ---------------- GEMM (f32x2) + attn epilogue ----------------
__global__ void gemm_kernel(const float* __restrict__ x, const float* __restrict__ W,
                            const float* __restrict__ att_src, const float* __restrict__ att_dst) {
    __shared__ float xsT[KCH][GR + XPAD];   // [k][row]  ~16.5KB
    __shared__ float Ws[KCH][HID];          // [k][col]   8KB

    const int tid  = threadIdx.x;
    const int row0 = blockIdx.x * GR;
    const int tr   = tid >> 3;   // 0..15
    const int tc   = tid & 7;    // 0..7

    unsigned long long acc[8][4];
    #pragma unroll
    for (int i = 0; i < 8; i++)
        #pragma unroll
        for (int j = 0; j < 4; j++) acc[i][j] = 0ull;

    #pragma unroll
    for (int ph = 0; ph < FIN / KCH; ph++) {
        #pragma unroll
        for (int it = 0; it < 8; it++) {
            int f  = it * 128 + tid;
            int r  = f >> 3;
            int k4 = f & 7;
            float4 v = make_float4(0.f, 0.f, 0.f, 0.f);
            if (row0 + r < NN)
                v = *(const float4*)&x[(long long)(row0 + r) * FIN + ph * KCH + k4 * 4];
            xsT[k4 * 4 + 0][r] = v.x;
            xsT[k4 * 4 + 1][r] = v.y;
            xsT[k4 * 4 + 2][r] = v.z;
            xsT[k4 * 4 + 3][r] = v.w;
        }
        #pragma unroll
        for (int it = 0; it < 4; it++) {
            int f  = it * 128 + tid;
            int kk = f >> 4;
            int c4 = f & 15;
            *(float4*)&Ws[kk][c4 * 4] = *(const float4*)&W[(ph * KCH + kk) * HID + c4 * 4];
        }
        __syncthreads();

        #pragma unroll 4
        for (int k = 0; k < KCH; k++) {
            float4 a0 = *(const float4*)&xsT[k][tr * 8];
            float4 a1 = *(const float4*)&xsT[k][tr * 8 + 4];
            const unsigned long long* bp = (const unsigned long long*)&Ws[k][tc * 8];
            unsigned long long b0 = bp[0], b1 = bp[1], b2 = bp[2], b3 = bp[3];
            float a[8] = {a0.x, a0.y, a0.z, a0.w, a1.x, a1.y, a1.z, a1.w};
            #pragma unroll
            for (int i = 0; i < 8; i++) {
                unsigned long long ai = pack2(a[i], a[i]);
                acc[i][0] = fma2(ai, b0, acc[i][0]);
                acc[i][1] = fma2(ai, b1, acc[i][1]);
                acc[i][2] = fma2(ai, b2, acc[i][2]);
                acc[i][3] = fma2(ai, b3, acc[i][3]);
            }
        }
        __syncthreads();
    }

    float as[8], ad[8];
    #pragma unroll
    for (int j = 0; j < 8; j++) { as[j] = att_src[tc * 8 + j]; ad[j] = att_dst[tc * 8 + j]; }

    float* redA = (float*)xsT;           // [128][8]
    float* redB = redA + GR * 8;         // [128][8]

    #pragma unroll
    for (int i = 0; i < 8; i++) {
        int row = tr * 8 + i;
        int r   = row0 + row;
        float2 c0 = unpack2(acc[i][0]);
        float2 c1 = unpack2(acc[i][1]);
        float2 c2 = unpack2(acc[i][2]);
        float2 c3 = unpack2(acc[i][3]);
        if (r < NN) {
            float4 v0 = make_float4(c0.x, c0.y, c1.x, c1.y);
            float4 v1 = make_float4(c2.x, c2.y, c3.x, c3.y);
            *(float4*)&g_h[(long long)r * HID + tc * 8]     = v0;
            *(float4*)&g_h[(long long)r * HID + tc * 8 + 4] = v1;
        }
        float pa = c0.x * as[0] + c0.y * as[1] + c1.x * as[2] + c1.y * as[3]
                 + c2.x * as[4] + c2.y * as[5] + c3.x * as[6] + c3.y * as[7];
        float pb = c0.x * ad[0] + c0.y * ad[1] + c1.x * ad[2] + c1.y * ad[3]
                 + c2.x * ad[4] + c2.y * ad[5] + c3.x * ad[6] + c3.y * ad[7];
        redA[row * 8 + tc] = pa;
        redB[row * 8 + tc] = pb;
    }
    __syncthreads();
    {
        int r = row0 + tid;
        if (r < NN) {
            float sa = 0.f, sb = 0.f;
            #pragma unroll
            for (int j = 0; j < 8; j++) { sa += redA[tid * 8 + j]; sb += redB[tid * 8 + j]; }
            g_asrc[r] = sa;
            g_adst[r] = sb;
        }
    }
}

// ---------------- edges: conversion + histogram + edge weights (2 edges/thread) ----
// runs AFTER gemm, so asrc/adst are available for weight precompute.
__global__ void edges_kernel(const void* ei) {
    int t  = blockIdx.x * blockDim.x + threadIdx.x;
    int i0 = t * 2;
    if (i0 >= EE) return;
    int is64 = g_is64;
    int s0, d0, s1 = 0, d1 = 0;
    int have2 = (i0 + 1 < EE);
    if (is64) {
        // two consecutive int64 src, two consecutive int64 dst: 16B loads
        longlong2 sv = *(const longlong2*)((const long long*)ei + i0);
        longlong2 dv = *(const longlong2*)((const long long*)ei + EE + i0);
        s0 = (int)sv.x; s1 = (int)sv.y;
        d0 = (int)dv.x; d1 = (int)dv.y;
    } else {
        int2 sv = *(const int2*)((const int*)ei + i0);
        int2 dv = *(const int2*)((const int*)ei + EE + i0);
        s0 = sv.x; s1 = sv.y;
        d0 = dv.x; d1 = dv.y;
    }
    // independent gathers, both issued before exp
    float e0 = g_asrc[s0] + g_adst[d0];
    float w0 = leaky_exp(e0);
    g_sd[i0] = make_int2(s0, d0);
    g_we[i0] = w0;
    atomicAdd(&g_count[d0], 1);
    if (have2) {
        float e1 = g_asrc[s1] + g_adst[d1];
        float w1 = leaky_exp(e1);
        g_sd[i0 + 1] = make_int2(s1, d1);
        g_we[i0 + 1] = w1;
        atomicAdd(&g_count[d1], 1);
    }
}

// ---------------- scan phase 1 (block sums) ----------------
__global__ void scan1_kernel() {
    __shared__ int wsum[NWARPS];
    int i = blockIdx.x * SCAN_B + threadIdx.x;
    int lane = threadIdx.x & 31;
    int warp = threadIdx.x >> 5;
    int c = (i < NN) ? g_count[i] : 0;
    int v = c;
    #pragma unroll
    for (int o = 16; o; o >>= 1) v += __shfl_xor_sync(0xffffffffu, v, o);
    if (lane == 0) wsum[warp] = v;
    __syncthreads();
    if (threadIdx.x == 0) {
        int s = 0;
        #pragma unroll
        for (int w = 0; w < NWARPS; w++) s += wsum[w];
        g_bsum[blockIdx.x] = s;
    }
}

// ---------------- scan phase 2: downsweep with redundant block-sum scan ----
__global__ void scan3_kernel() {
    __shared__ int wpre[NWARPS];
    __shared__ int bsc[SCAN_B];
    int t = threadIdx.x;
    int bv = (t < SCAN_G) ? g_bsum[t] : 0;
    bsc[t] = bv;
    __syncthreads();
    for (int off = 1; off < SCAN_B; off <<= 1) {
        int add = (t >= off) ? bsc[t - off] : 0;
        __syncthreads();
        bsc[t] += add;
        __syncthreads();
    }
    int blockPre = (blockIdx.x == 0) ? 0 : bsc[blockIdx.x - 1];
    if (blockIdx.x == 0 && t == 0) g_offsets[NN] = ET;

    int i = blockIdx.x * SCAN_B + t;
    int lane = t & 31;
    int warp = t >> 5;
    int c = (i < NN) ? g_count[i] : 0;
    int v = c;
    #pragma unroll
    for (int o = 1; o < 32; o <<= 1) {
        int u = __shfl_up_sync(0xffffffffu, v, o);
        if (lane >= o) v += u;
    }
    if (lane == 31) wpre[warp] = v;
    __syncthreads();
    if (warp == 0) {
        int u = (lane < NWARPS) ? wpre[lane] : 0;
        int s = u;
        #pragma unroll
        for (int o = 1; o < 32; o <<= 1) {
            int t2 = __shfl_up_sync(0xffffffffu, s, o);
            if (lane >= o) s += t2;
        }
        if (lane < NWARPS) wpre[lane] = s - u;
    }
    __syncthreads();
    if (i < NN) {
        int off = blockPre + wpre[warp] + (v - c);   // exclusive
        g_offsets[i] = off;
        g_cursor[i]  = off;
    }
}

// ---------------- scatter into CSR (weights precomputed; 2 edges/thread) ----
__global__ void scatter_kernel() {
    int t  = blockIdx.x * blockDim.x + threadIdx.x;
    int i0 = t * 2;
    if (i0 >= ET) return;

    // edge 0
    int s0, d0; float w0;
    if (i0 < EE) { int2 sd = g_sd[i0]; s0 = sd.x; d0 = sd.y; w0 = g_we[i0]; }
    else {
        s0 = d0 = i0 - EE;
        w0 = leaky_exp(g_asrc[s0] + g_adst[s0]);   // coalesced (sequential nodes)
    }
    // edge 1
    int i1 = i0 + 1;
    int have2 = (i1 < ET);
    int s1 = 0, d1 = 0; float w1 = 0.f;
    if (have2) {
        if (i1 < EE) { int2 sd = g_sd[i1]; s1 = sd.x; d1 = sd.y; w1 = g_we[i1]; }
        else {
            s1 = d1 = i1 - EE;
            w1 = leaky_exp(g_asrc[s1] + g_adst[s1]);
        }
    }
    // two independent atomic+store chains
    int p0 = atomicAdd(&g_cursor[d0], 1);
    int p1 = have2 ? atomicAdd(&g_cursor[d1], 1) : 0;
    EW e0; e0.s = s0; e0.w = w0;
    g_ew[p0] = e0;
    if (have2) { EW e1; e1.s = s1; e1.w = w1; g_ew[p1] = e1; }
}

// ---------------- aggregate (packed weights) + ELU + fc fold ----------------
__global__ void aggregate_kernel(const float* __restrict__ bias,
                                 const float* __restrict__ fcw,
                                 const float* __restrict__ fcb) {
    int n    = (blockIdx.x * blockDim.x + threadIdx.x) >> 5;
    int lane = threadIdx.x & 31;
    if (n >= NN) return;
    int sub  = lane >> 4;        // 0/1: parity class of edges
    int l16  = lane & 15;        // column group

    int start = g_offsets[n];
    int end   = g_offsets[n + 1];

    float4 acc = make_float4(0.f, 0.f, 0.f, 0.f);
    float wsum = 0.f;
    int i = start + sub;
    for (; i + 2 < end; i += 4) {
        EW e0 = g_ew[i];
        EW e1 = g_ew[i + 2];
        float4 h0 = *(const float4*)&g_h[(long long)e0.s * HID + l16 * 4];
        float4 h1 = *(const float4*)&g_h[(long long)e1.s * HID + l16 * 4];
        wsum += e0.w + e1.w;
        acc.x = fmaf(e0.w, h0.x, fmaf(e1.w, h1.x, acc.x));
        acc.y = fmaf(e0.w, h0.y, fmaf(e1.w, h1.y, acc.y));
        acc.z = fmaf(e0.w, h0.z, fmaf(e1.w, h1.z, acc.z));
        acc.w = fmaf(e0.w, h0.w, fmaf(e1.w, h1.w, acc.w));
    }
    if (i < end) {
        EW e0 = g_ew[i];
        float4 h0 = *(const float4*)&g_h[(long long)e0.s * HID + l16 * 4];
        wsum += e0.w;
        acc.x = fmaf(e0.w, h0.x, acc.x);
        acc.y = fmaf(e0.w, h0.y, acc.y);
        acc.z = fmaf(e0.w, h0.z, acc.z);
        acc.w = fmaf(e0.w, h0.w, acc.w);
    }
    wsum += __shfl_xor_sync(0xffffffffu, wsum, 16);
    acc.x += __shfl_down_sync(0xffffffffu, acc.x, 16);
    acc.y += __shfl_down_sync(0xffffffffu, acc.y, 16);
    acc.z += __shfl_down_sync(0xffffffffu, acc.z, 16);
    acc.w += __shfl_down_sync(0xffffffffu, acc.w, 16);

    float inv = 1.0f / wsum;
    float4 b  = *(const float4*)&bias[l16 * 4];
    float o0 = acc.x * inv + b.x;
    float o1 = acc.y * inv + b.y;
    float o2 = acc.z * inv + b.z;
    float o3 = acc.w * inv + b.w;
    o0 = (o0 > 0.f) ? o0 : expm1f(o0);
    o1 = (o1 > 0.f) ? o1 : expm1f(o1);
    o2 = (o2 > 0.f) ? o2 : expm1f(o2);
    o3 = (o3 > 0.f) ? o3 : expm1f(o3);

    float4 f0 = *(const float4*)&fcw[l16 * 4];
    float4 f1 = *(const float4*)&fcw[HID + l16 * 4];
    float p0 = o0 * f0.x + o1 * f0.y + o2 * f0.z + o3 * f0.w;
    float p1 = o0 * f1.x + o1 * f1.y + o2 * f1.z + o3 * f1.w;
    #pragma unroll
    for (int o = 8; o; o >>= 1) {
        p0 += __shfl_xor_sync(0xffffffffu, p0, o);
        p1 += __shfl_xor_sync(0xffffffffu, p1, o);
    }
    if (lane == 0) {
        g_s0[n] = p0 + fcb[0];   // fold fc bias into s0
        g_s1[n] = p1;
    }
}

// ---------------- per-edge scores (8 edges per thread, packed pairs) ----------------
__global__ void score_kernel(float* __restrict__ out) {
    int t = blockIdx.x * blockDim.x + threadIdx.x;
    int e0 = t * 8;
    if (e0 >= EE) return;
    if (e0 + 8 <= EE) {
        float4 r0, r1;
        {
            int4 p01 = *(const int4*)&g_sd[e0];
            int4 p23 = *(const int4*)&g_sd[e0 + 2];
            r0.x = g_s0[p01.x] + g_s1[p01.y];
            r0.y = g_s0[p01.z] + g_s1[p01.w];
            r0.z = g_s0[p23.x] + g_s1[p23.y];
            r0.w = g_s0[p23.z] + g_s1[p23.w];
        }
        {
            int4 p45 = *(const int4*)&g_sd[e0 + 4];
            int4 p67 = *(const int4*)&g_sd[e0 + 6];
            r1.x = g_s0[p45.x] + g_s1[p45.y];
            r1.y = g_s0[p45.z] + g_s1[p45.w];
            r1.z = g_s0[p67.x] + g_s1[p67.y];
            r1.w = g_s0[p67.z] + g_s1[p67.w];
        }
        *(float4*)&out[e0]     = r0;
        *(float4*)&out[e0 + 4] = r1;
    } else {
        for (int e = e0; e < EE; e++) {
            int2 sd = g_sd[e];
            out[e] = g_s0[sd.x] + g_s1[sd.y];
        }
    }
}

// ---------------- launch ----------------
extern "C" void kernel_launch(void* const* d_in, const int* in_sizes, int n_in,
                              void* d_out, int out_size) {
    const float* x   = (const float*)d_in[0];
    const void*  ei  = d_in[1];
    const float* W   = (const float*)d_in[2];
    const float* asv = (const float*)d_in[3];
    const float* adv = (const float*)d_in[4];
    const float* bias= (const float*)d_in[5];
    const float* fcw = (const float*)d_in[6];
    const float* fcb = (const float*)d_in[7];
    float* out = (float*)d_out;

    init_kernel<<<(NN + 255) / 256, 256>>>((const int*)ei);
    gemm_kernel<<<(NN + GR - 1) / GR, 128>>>(x, W, asv, adv);
    edges_kernel<<<(EE / 2 + 255) / 256, 256>>>(ei);
    scan1_kernel<<<SCAN_G, SCAN_B>>>();
    scan3_kernel<<<SCAN_G, SCAN_B>>>();
    scatter_kernel<<<((ET + 1) / 2 + 255) / 256, 256>>>();
    aggregate_kernel<<<(NN * 32 + 255) / 256, 256>>>(bias, fcw, fcb);
    score_kernel<<<(EE / 8 + 255) / 256, 256>>>(out);
}

// round 10
// speedup vs baseline: 1.1900x; 1.1900x over previous
#include <cuda_runtime.h>
#include <math.h>

#define NN   50000
#define EE   800000
#define ET   (EE + NN)        // edges + self loops
#define FIN  128
#define HID  64
#define NEG_SLOPE 0.2f

#define SCAN_B   256
#define SCAN_G   ((NN + SCAN_B - 1) / SCAN_B)   // 196
#define NWARPS   (SCAN_B / 32)                  // 8

#define GR   128              // gemm rows per block
#define KCH  32               // gemm k-chunk per phase
#define XPAD 4                // row padding for transpose store

struct __align__(8) EW { int s; float w; };

// ---------------- scratch (device globals; no allocs allowed) ----------------
__device__ float g_h[NN * HID];        // x @ W
__device__ float g_asrc[NN];
__device__ float g_adst[NN];
__device__ int   g_count[NN];          // degree histogram
__device__ int   g_cursor[NN];         // scatter cursors
__device__ int   g_offsets[NN + 1];    // CSR offsets
__device__ EW    g_ew[ET];             // (src, weight) per CSR slot
__device__ int2  g_sd[EE];             // packed (src,dst) int32
__device__ float g_s0[NN];
__device__ float g_s1[NN];
__device__ int   g_bsum[SCAN_G];       // per-block count sums
__device__ int   g_is64;

__device__ __forceinline__ int edge_at(const void* p, long long i, int is64) {
    return is64 ? (int)((const long long*)p)[i] : ((const int*)p)[i];
}

// packed fp32x2 helpers (Blackwell)
__device__ __forceinline__ unsigned long long fma2(unsigned long long a,
                                                   unsigned long long b,
                                                   unsigned long long c) {
    unsigned long long d;
    asm("fma.rn.f32x2 %0, %1, %2, %3;" : "=l"(d) : "l"(a), "l"(b), "l"(c));
    return d;
}
__device__ __forceinline__ unsigned long long pack2(float lo, float hi) {
    unsigned long long r;
    asm("mov.b64 %0, {%1, %2};" : "=l"(r) : "f"(lo), "f"(hi));
    return r;
}
__device__ __forceinline__ float2 unpack2(unsigned long long v) {
    float2 r;
    asm("mov.b64 {%0, %1}, %2;" : "=f"(r.x), "=f"(r.y) : "l"(v));
    return r;
}

// ---------------- init: counts=1 (self-loop pre-counted) + dtype detect ----
__global__ void init_kernel(const int* ew) {
    int i = blockIdx.x * blockDim.x + threadIdx.x;
    if (i < NN) g_count[i] = 1;          // self loop contributes 1 per node
    if (i == 0) {
        int all0 = 1;
        #pragma unroll 8
        for (int j = 0; j < 64; j++) {
            if (ew[2 * j + 1] != 0) { all0 = 0; break; }
        }
        g_is64 = all0;
    }
}

// ---------------- GEMM (f32x2) + attn epilogue ----------------
__global__ void gemm_kernel(const float* __restrict__ x, const float* __restrict__ W,
                            const float* __restrict__ att_src, const float* __restrict__ att_dst) {
    __shared__ float xsT[KCH][GR + XPAD];   // [k][row]  ~16.5KB
    __shared__ float Ws[KCH][HID];          // [k][col]   8KB

    const int tid  = threadIdx.x;
    const int row0 = blockIdx.x * GR;
    const int tr   = tid >> 3;   // 0..15
    const int tc   = tid & 7;    // 0..7

    unsigned long long acc[8][4];
    #pragma unroll
    for (int i = 0; i < 8; i++)
        #pragma unroll
        for (int j = 0; j < 4; j++) acc[i][j] = 0ull;

    #pragma unroll
    for (int ph = 0; ph < FIN / KCH; ph++) {
        #pragma unroll
        for (int it = 0; it < 8; it++) {
            int f  = it * 128 + tid;
            int r  = f >> 3;
            int k4 = f & 7;
            float4 v = make_float4(0.f, 0.f, 0.f, 0.f);
            if (row0 + r < NN)
                v = *(const float4*)&x[(long long)(row0 + r) * FIN + ph * KCH + k4 * 4];
            xsT[k4 * 4 + 0][r] = v.x;
            xsT[k4 * 4 + 1][r] = v.y;
            xsT[k4 * 4 + 2][r] = v.z;
            xsT[k4 * 4 + 3][r] = v.w;
        }
        #pragma unroll
        for (int it = 0; it < 4; it++) {
            int f  = it * 128 + tid;
            int kk = f >> 4;
            int c4 = f & 15;
            *(float4*)&Ws[kk][c4 * 4] = *(const float4*)&W[(ph * KCH + kk) * HID + c4 * 4];
        }
        __syncthreads();

        #pragma unroll 4
        for (int k = 0; k < KCH; k++) {
            float4 a0 = *(const float4*)&xsT[k][tr * 8];
            float4 a1 = *(const float4*)&xsT[k][tr * 8 + 4];
            const unsigned long long* bp = (const unsigned long long*)&Ws[k][tc * 8];
            unsigned long long b0 = bp[0], b1 = bp[1], b2 = bp[2], b3 = bp[3];
            float a[8] = {a0.x, a0.y, a0.z, a0.w, a1.x, a1.y, a1.z, a1.w};
            #pragma unroll
            for (int i = 0; i < 8; i++) {
                unsigned long long ai = pack2(a[i], a[i]);
                acc[i][0] = fma2(ai, b0, acc[i][0]);
                acc[i][1] = fma2(ai, b1, acc[i][1]);
                acc[i][2] = fma2(ai, b2, acc[i][2]);
                acc[i][3] = fma2(ai, b3, acc[i][3]);
            }
        }
        __syncthreads();
    }

    float as[8], ad[8];
    #pragma unroll
    for (int j = 0; j < 8; j++) { as[j] = att_src[tc * 8 + j]; ad[j] = att_dst[tc * 8 + j]; }

    float* redA = (float*)xsT;           // [128][8]
    float* redB = redA + GR * 8;         // [128][8]

    #pragma unroll
    for (int i = 0; i < 8; i++) {
        int row = tr * 8 + i;
        int r   = row0 + row;
        float2 c0 = unpack2(acc[i][0]);
        float2 c1 = unpack2(acc[i][1]);
        float2 c2 = unpack2(acc[i][2]);
        float2 c3 = unpack2(acc[i][3]);
        if (r < NN) {
            float4 v0 = make_float4(c0.x, c0.y, c1.x, c1.y);
            float4 v1 = make_float4(c2.x, c2.y, c3.x, c3.y);
            *(float4*)&g_h[(long long)r * HID + tc * 8]     = v0;
            *(float4*)&g_h[(long long)r * HID + tc * 8 + 4] = v1;
        }
        float pa = c0.x * as[0] + c0.y * as[1] + c1.x * as[2] + c1.y * as[3]
                 + c2.x * as[4] + c2.y * as[5] + c3.x * as[6] + c3.y * as[7];
        float pb = c0.x * ad[0] + c0.y * ad[1] + c1.x * ad[2] + c1.y * ad[3]
                 + c2.x * ad[4] + c2.y * ad[5] + c3.x * ad[6] + c3.y * ad[7];
        redA[row * 8 + tc] = pa;
        redB[row * 8 + tc] = pb;
    }
    __syncthreads();
    {
        int r = row0 + tid;
        if (r < NN) {
            float sa = 0.f, sb = 0.f;
            #pragma unroll
            for (int j = 0; j < 8; j++) { sa += redA[tid * 8 + j]; sb += redB[tid * 8 + j]; }
            g_asrc[r] = sa;
            g_adst[r] = sb;
        }
    }
}

// ---------------- edges: int64->int32 packed conversion + dst histogram ----------------
__global__ void edges_kernel(const void* ei) {
    int i = blockIdx.x * blockDim.x + threadIdx.x;
    if (i >= EE) return;
    int is64 = g_is64;
    int s = edge_at(ei, i, is64);
    int d = edge_at(ei, (long long)EE + i, is64);
    g_sd[i] = make_int2(s, d);
    atomicAdd(&g_count[d], 1);
}

// ---------------- scan phase 1 (block sums) ----------------
__global__ void scan1_kernel() {
    __shared__ int wsum[NWARPS];
    int i = blockIdx.x * SCAN_B + threadIdx.x;
    int lane = threadIdx.x & 31;
    int warp = threadIdx.x >> 5;
    int c = (i < NN) ? g_count[i] : 0;
    int v = c;
    #pragma unroll
    for (int o = 16; o; o >>= 1) v += __shfl_xor_sync(0xffffffffu, v, o);
    if (lane == 0) wsum[warp] = v;
    __syncthreads();
    if (threadIdx.x == 0) {
        int s = 0;
        #pragma unroll
        for (int w = 0; w < NWARPS; w++) s += wsum[w];
        g_bsum[blockIdx.x] = s;
    }
}

// ---------------- scan phase 2: downsweep with redundant block-sum scan ----
__global__ void scan3_kernel() {
    __shared__ int wpre[NWARPS];
    __shared__ int bsc[SCAN_B];
    int t = threadIdx.x;
    int bv = (t < SCAN_G) ? g_bsum[t] : 0;
    bsc[t] = bv;
    __syncthreads();
    for (int off = 1; off < SCAN_B; off <<= 1) {
        int add = (t >= off) ? bsc[t - off] : 0;
        __syncthreads();
        bsc[t] += add;
        __syncthreads();
    }
    int blockPre = (blockIdx.x == 0) ? 0 : bsc[blockIdx.x - 1];
    if (blockIdx.x == 0 && t == 0) g_offsets[NN] = ET;

    int i = blockIdx.x * SCAN_B + t;
    int lane = t & 31;
    int warp = t >> 5;
    int c = (i < NN) ? g_count[i] : 0;
    int v = c;
    #pragma unroll
    for (int o = 1; o < 32; o <<= 1) {
        int u = __shfl_up_sync(0xffffffffu, v, o);
        if (lane >= o) v += u;
    }
    if (lane == 31) wpre[warp] = v;
    __syncthreads();
    if (warp == 0) {
        int u = (lane < NWARPS) ? wpre[lane] : 0;
        int s = u;
        #pragma unroll
        for (int o = 1; o < 32; o <<= 1) {
            int t2 = __shfl_up_sync(0xffffffffu, s, o);
            if (lane >= o) s += t2;
        }
        if (lane < NWARPS) wpre[lane] = s - u;
    }
    __syncthreads();
    if (i < NN) {
        int off = blockPre + wpre[warp] + (v - c);   // exclusive
        g_offsets[i] = off;
        g_cursor[i]  = off;
    }
}

// ---------------- scatter into CSR + precompute edge weights (packed) ----------------
__global__ void scatter_kernel() {
    int i = blockIdx.x * blockDim.x + threadIdx.x;
    if (i >= ET) return;
    int s, d;
    if (i < EE) { int2 sd = g_sd[i]; s = sd.x; d = sd.y; }
    else        { s = d = i - EE; }
    int pos = atomicAdd(&g_cursor[d], 1);
    float e = g_asrc[s] + g_adst[d];
    e = (e > 0.f) ? e : NEG_SLOPE * e;
    EW ew; ew.s = s; ew.w = __expf(e);
    g_ew[pos] = ew;                       // single STG.64
}

// ---------------- aggregate (packed weights) + ELU + fc fold ----------------
__global__ void aggregate_kernel(const float* __restrict__ bias,
                                 const float* __restrict__ fcw,
                                 const float* __restrict__ fcb) {
    int n    = (blockIdx.x * blockDim.x + threadIdx.x) >> 5;
    int lane = threadIdx.x & 31;
    if (n >= NN) return;
    int sub  = lane >> 4;        // 0/1: parity class of edges
    int l16  = lane & 15;        // column group

    int start = g_offsets[n];
    int end   = g_offsets[n + 1];

    float4 acc = make_float4(0.f, 0.f, 0.f, 0.f);
    float wsum = 0.f;
    int i = start + sub;
    for (; i + 2 < end; i += 4) {
        EW e0 = g_ew[i];
        EW e1 = g_ew[i + 2];
        float4 h0 = *(const float4*)&g_h[(long long)e0.s * HID + l16 * 4];
        float4 h1 = *(const float4*)&g_h[(long long)e1.s * HID + l16 * 4];
        wsum += e0.w + e1.w;
        acc.x = fmaf(e0.w, h0.x, fmaf(e1.w, h1.x, acc.x));
        acc.y = fmaf(e0.w, h0.y, fmaf(e1.w, h1.y, acc.y));
        acc.z = fmaf(e0.w, h0.z, fmaf(e1.w, h1.z, acc.z));
        acc.w = fmaf(e0.w, h0.w, fmaf(e1.w, h1.w, acc.w));
    }
    if (i < end) {
        EW e0 = g_ew[i];
        float4 h0 = *(const float4*)&g_h[(long long)e0.s * HID + l16 * 4];
        wsum += e0.w;
        acc.x = fmaf(e0.w, h0.x, acc.x);
        acc.y = fmaf(e0.w, h0.y, acc.y);
        acc.z = fmaf(e0.w, h0.z, acc.z);
        acc.w = fmaf(e0.w, h0.w, acc.w);
    }
    wsum += __shfl_xor_sync(0xffffffffu, wsum, 16);
    acc.x += __shfl_down_sync(0xffffffffu, acc.x, 16);
    acc.y += __shfl_down_sync(0xffffffffu, acc.y, 16);
    acc.z += __shfl_down_sync(0xffffffffu, acc.z, 16);
    acc.w += __shfl_down_sync(0xffffffffu, acc.w, 16);

    float inv = 1.0f / wsum;
    float4 b  = *(const float4*)&bias[l16 * 4];
    float o0 = acc.x * inv + b.x;
    float o1 = acc.y * inv + b.y;
    float o2 = acc.z * inv + b.z;
    float o3 = acc.w * inv + b.w;
    o0 = (o0 > 0.f) ? o0 : expm1f(o0);
    o1 = (o1 > 0.f) ? o1 : expm1f(o1);
    o2 = (o2 > 0.f) ? o2 : expm1f(o2);
    o3 = (o3 > 0.f) ? o3 : expm1f(o3);

    float4 f0 = *(const float4*)&fcw[l16 * 4];
    float4 f1 = *(const float4*)&fcw[HID + l16 * 4];
    float p0 = o0 * f0.x + o1 * f0.y + o2 * f0.z + o3 * f0.w;
    float p1 = o0 * f1.x + o1 * f1.y + o2 * f1.z + o3 * f1.w;
    #pragma unroll
    for (int o = 8; o; o >>= 1) {
        p0 += __shfl_xor_sync(0xffffffffu, p0, o);
        p1 += __shfl_xor_sync(0xffffffffu, p1, o);
    }
    if (lane == 0) {
        g_s0[n] = p0 + fcb[0];   // fold fc bias into s0
        g_s1[n] = p1;
    }
}

// ---------------- per-edge scores (4 edges per thread, packed pairs) ----------------
__global__ void score_kernel(float* __restrict__ out) {
    int t = blockIdx.x * blockDim.x + threadIdx.x;
    int e0 = t * 4;
    if (e0 >= EE) return;
    if (e0 + 4 <= EE) {
        int4 p01 = *(const int4*)&g_sd[e0];       // (s0,d0,s1,d1)
        int4 p23 = *(const int4*)&g_sd[e0 + 2];   // (s2,d2,s3,d3)
        float4 r;
        r.x = g_s0[p01.x] + g_s1[p01.y];
        r.y = g_s0[p01.z] + g_s1[p01.w];
        r.z = g_s0[p23.x] + g_s1[p23.y];
        r.w = g_s0[p23.z] + g_s1[p23.w];
        *(float4*)&out[e0] = r;
    } else {
        for (int e = e0; e < EE; e++) {
            int2 sd = g_sd[e];
            out[e] = g_s0[sd.x] + g_s1[sd.y];
        }
    }
}

// ---------------- launch: fork-join overlap of gemm with edge chain ----------------
extern "C" void kernel_launch(void* const* d_in, const int* in_sizes, int n_in,
                              void* d_out, int out_size) {
    const float* x   = (const float*)d_in[0];
    const void*  ei  = d_in[1];
    const float* W   = (const float*)d_in[2];
    const float* asv = (const float*)d_in[3];
    const float* adv = (const float*)d_in[4];
    const float* bias= (const float*)d_in[5];
    const float* fcw = (const float*)d_in[6];
    const float* fcb = (const float*)d_in[7];
    float* out = (float*)d_out;

    // one-time host-side stream/event setup (no device allocations)
    static cudaStream_t s2 = nullptr;
    static cudaEvent_t evFork = nullptr, evJoin = nullptr;
    if (s2 == nullptr) {
        cudaStreamCreateWithFlags(&s2, cudaStreamNonBlocking);
        cudaEventCreateWithFlags(&evFork, cudaEventDisableTiming);
        cudaEventCreateWithFlags(&evJoin, cudaEventDisableTiming);
    }

    init_kernel<<<(NN + 255) / 256, 256>>>((const int*)ei);

    // fork: gemm on s2, edge chain on default stream (independent of gemm)
    cudaEventRecord(evFork, 0);
    cudaStreamWaitEvent(s2, evFork, 0);
    gemm_kernel<<<(NN + GR - 1) / GR, 128, 0, s2>>>(x, W, asv, adv);

    edges_kernel<<<(EE + 255) / 256, 256>>>(ei);
    scan1_kernel<<<SCAN_G, SCAN_B>>>();
    scan3_kernel<<<SCAN_G, SCAN_B>>>();

    // join: scatter needs both gemm (asrc/adst) and scan (cursor)
    cudaEventRecord(evJoin, s2);
    cudaStreamWaitEvent(0, evJoin, 0);

    scatter_kernel<<<(ET + 255) / 256, 256>>>();
    aggregate_kernel<<<(NN * 32 + 255) / 256, 256>>>(bias, fcw, fcb);
    score_kernel<<<(EE / 4 + 255) / 256, 256>>>(out);
}

// round 11
// speedup vs baseline: 1.1927x; 1.0022x over previous
#include <cuda_runtime.h>
#include <math.h>

#define NN   50000
#define EE   800000
#define ET   (EE + NN)        // edges + self loops
#define FIN  128
#define HID  64
#define NEG_SLOPE 0.2f

#define SCAN_B   256
#define SCAN_G   ((NN + SCAN_B - 1) / SCAN_B)   // 196
#define NWARPS   (SCAN_B / 32)                  // 8

#define GR   128              // gemm rows per block
#define KCH  32               // gemm k-chunk per phase
#define XPAD 4                // row padding for transpose store

struct __align__(8) EW { int s; float w; };

// ---------------- scratch (device globals; no allocs allowed) ----------------
__device__ float g_h[NN * HID];        // x @ W
__device__ float g_asrc[NN];
__device__ float g_adst[NN];
__device__ int   g_count[NN];          // degree histogram
__device__ int   g_cursor[NN];         // scatter cursors
__device__ int   g_offsets[NN + 1];    // CSR offsets
__device__ EW    g_ew[ET];             // (src, weight) per CSR slot
__device__ int2  g_sd[EE];             // packed (src,dst) int32
__device__ float g_s0[NN];
__device__ float g_s1[NN];
__device__ int   g_bsum[SCAN_G];       // per-block count sums
__device__ int   g_is64;

// packed fp32x2 helpers (Blackwell)
__device__ __forceinline__ unsigned long long fma2(unsigned long long a,
                                                   unsigned long long b,
                                                   unsigned long long c) {
    unsigned long long d;
    asm("fma.rn.f32x2 %0, %1, %2, %3;" : "=l"(d) : "l"(a), "l"(b), "l"(c));
    return d;
}
__device__ __forceinline__ unsigned long long pack2(float lo, float hi) {
    unsigned long long r;
    asm("mov.b64 %0, {%1, %2};" : "=l"(r) : "f"(lo), "f"(hi));
    return r;
}
__device__ __forceinline__ float2 unpack2(unsigned long long v) {
    float2 r;
    asm("mov.b64 {%0, %1}, %2;" : "=f"(r.x), "=f"(r.y) : "l"(v));
    return r;
}

// ---------------- init: counts=1 (self-loop pre-counted) + dtype detect ----
__global__ void init_kernel(const int* ew) {
    int i = blockIdx.x * blockDim.x + threadIdx.x;
    if (i < NN) g_count[i] = 1;          // self loop contributes 1 per node
    if (i == 0) {
        int all0 = 1;
        #pragma unroll 8
        for (int j = 0; j < 64; j++) {
            if (ew[2 * j + 1] != 0) { all0 = 0; break; }
        }
        g_is64 = all0;
    }
}

// ---------------- GEMM (f32x2) + attn epilogue ----------------
__global__ void gemm_kernel(const float* __restrict__ x, const float* __restrict__ W,
                            const float* __restrict__ att_src, const float* __restrict__ att_dst) {
    __shared__ float xsT[KCH][GR + XPAD];   // [k][row]  ~16.5KB
    __shared__ float Ws[KCH][HID];          // [k][col]   8KB

    const int tid  = threadIdx.x;
    const int row0 = blockIdx.x * GR;
    const int tr   = tid >> 3;   // 0..15
    const int tc   = tid & 7;    // 0..7

    unsigned long long acc[8][4];
    #pragma unroll
    for (int i = 0; i < 8; i++)
        #pragma unroll
        for (int j = 0; j < 4; j++) acc[i][j] = 0ull;

    #pragma unroll
    for (int ph = 0; ph < FIN / KCH; ph++) {
        #pragma unroll
        for (int it = 0; it < 8; it++) {
            int f  = it * 128 + tid;
            int r  = f >> 3;
            int k4 = f & 7;
            float4 v = make_float4(0.f, 0.f, 0.f, 0.f);
            if (row0 + r < NN)
                v = *(const float4*)&x[(long long)(row0 + r) * FIN + ph * KCH + k4 * 4];
            xsT[k4 * 4 + 0][r] = v.x;
            xsT[k4 * 4 + 1][r] = v.y;
            xsT[k4 * 4 + 2][r] = v.z;
            xsT[k4 * 4 + 3][r] = v.w;
        }
        #pragma unroll
        for (int it = 0; it < 4; it++) {
            int f  = it * 128 + tid;
            int kk = f >> 4;
            int c4 = f & 15;
            *(float4*)&Ws[kk][c4 * 4] = *(const float4*)&W[(ph * KCH + kk) * HID + c4 * 4];
        }
        __syncthreads();

        #pragma unroll 4
        for (int k = 0; k < KCH; k++) {
            float4 a0 = *(const float4*)&xsT[k][tr * 8];
            float4 a1 = *(const float4*)&xsT[k][tr * 8 + 4];
            const unsigned long long* bp = (const unsigned long long*)&Ws[k][tc * 8];
            unsigned long long b0 = bp[0], b1 = bp[1], b2 = bp[2], b3 = bp[3];
            float a[8] = {a0.x, a0.y, a0.z, a0.w, a1.x, a1.y, a1.z, a1.w};
            #pragma unroll
            for (int i = 0; i < 8; i++) {
                unsigned long long ai = pack2(a[i], a[i]);
                acc[i][0] = fma2(ai, b0, acc[i][0]);
                acc[i][1] = fma2(ai, b1, acc[i][1]);
                acc[i][2] = fma2(ai, b2, acc[i][2]);
                acc[i][3] = fma2(ai, b3, acc[i][3]);
            }
        }
        __syncthreads();
    }

    float as[8], ad[8];
    #pragma unroll
    for (int j = 0; j < 8; j++) { as[j] = att_src[tc * 8 + j]; ad[j] = att_dst[tc * 8 + j]; }

    float* redA = (float*)xsT;           // [128][8]
    float* redB = redA + GR * 8;         // [128][8]

    #pragma unroll
    for (int i = 0; i < 8; i++) {
        int row = tr * 8 + i;
        int r   = row0 + row;
        float2 c0 = unpack2(acc[i][0]);
        float2 c1 = unpack2(acc[i][1]);
        float2 c2 = unpack2(acc[i][2]);
        float2 c3 = unpack2(acc[i][3]);
        if (r < NN) {
            float4 v0 = make_float4(c0.x, c0.y, c1.x, c1.y);
            float4 v1 = make_float4(c2.x, c2.y, c3.x, c3.y);
            *(float4*)&g_h[(long long)r * HID + tc * 8]     = v0;
            *(float4*)&g_h[(long long)r * HID + tc * 8 + 4] = v1;
        }
        float pa = c0.x * as[0] + c0.y * as[1] + c1.x * as[2] + c1.y * as[3]
                 + c2.x * as[4] + c2.y * as[5] + c3.x * as[6] + c3.y * as[7];
        float pb = c0.x * ad[0] + c0.y * ad[1] + c1.x * ad[2] + c1.y * ad[3]
                 + c2.x * ad[4] + c2.y * ad[5] + c3.x * ad[6] + c3.y * ad[7];
        redA[row * 8 + tc] = pa;
        redB[row * 8 + tc] = pb;
    }
    __syncthreads();
    {
        int r = row0 + tid;
        if (r < NN) {
            float sa = 0.f, sb = 0.f;
            #pragma unroll
            for (int j = 0; j < 8; j++) { sa += redA[tid * 8 + j]; sb += redB[tid * 8 + j]; }
            g_asrc[r] = sa;
            g_adst[r] = sb;
        }
    }
}

// ---------------- edges: packed conversion + dst histogram (2 edges/thread) ----
__global__ void edges_kernel(const void* ei) {
    int t  = blockIdx.x * blockDim.x + threadIdx.x;
    int i0 = t * 2;
    if (i0 >= EE) return;
    int is64 = g_is64;
    int s0, d0, s1, d1;
    if (is64) {
        longlong2 sv = *(const longlong2*)((const long long*)ei + i0);
        longlong2 dv = *(const longlong2*)((const long long*)ei + EE + i0);
        s0 = (int)sv.x; s1 = (int)sv.y;
        d0 = (int)dv.x; d1 = (int)dv.y;
    } else {
        int2 sv = *(const int2*)((const int*)ei + i0);
        int2 dv = *(const int2*)((const int*)ei + EE + i0);
        s0 = sv.x; s1 = sv.y;
        d0 = dv.x; d1 = dv.y;
    }
    g_sd[i0] = make_int2(s0, d0);
    atomicAdd(&g_count[d0], 1);
    if (i0 + 1 < EE) {
        g_sd[i0 + 1] = make_int2(s1, d1);
        atomicAdd(&g_count[d1], 1);
    }
}

// ---------------- scan phase 1 (block sums) ----------------
__global__ void scan1_kernel() {
    __shared__ int wsum[NWARPS];
    int i = blockIdx.x * SCAN_B + threadIdx.x;
    int lane = threadIdx.x & 31;
    int warp = threadIdx.x >> 5;
    int c = (i < NN) ? g_count[i] : 0;
    int v = c;
    #pragma unroll
    for (int o = 16; o; o >>= 1) v += __shfl_xor_sync(0xffffffffu, v, o);
    if (lane == 0) wsum[warp] = v;
    __syncthreads();
    if (threadIdx.x == 0) {
        int s = 0;
        #pragma unroll
        for (int w = 0; w < NWARPS; w++) s += wsum[w];
        g_bsum[blockIdx.x] = s;
    }
}

// ---------------- scan phase 2: downsweep with redundant block-sum scan ----
__global__ void scan3_kernel() {
    __shared__ int wpre[NWARPS];
    __shared__ int bsc[SCAN_B];
    int t = threadIdx.x;
    int bv = (t < SCAN_G) ? g_bsum[t] : 0;
    bsc[t] = bv;
    __syncthreads();
    for (int off = 1; off < SCAN_B; off <<= 1) {
        int add = (t >= off) ? bsc[t - off] : 0;
        __syncthreads();
        bsc[t] += add;
        __syncthreads();
    }
    int blockPre = (blockIdx.x == 0) ? 0 : bsc[blockIdx.x - 1];
    if (blockIdx.x == 0 && t == 0) g_offsets[NN] = ET;

    int i = blockIdx.x * SCAN_B + t;
    int lane = t & 31;
    int warp = t >> 5;
    int c = (i < NN) ? g_count[i] : 0;
    int v = c;
    #pragma unroll
    for (int o = 1; o < 32; o <<= 1) {
        int u = __shfl_up_sync(0xffffffffu, v, o);
        if (lane >= o) v += u;
    }
    if (lane == 31) wpre[warp] = v;
    __syncthreads();
    if (warp == 0) {
        int u = (lane < NWARPS) ? wpre[lane] : 0;
        int s = u;
        #pragma unroll
        for (int o = 1; o < 32; o <<= 1) {
            int t2 = __shfl_up_sync(0xffffffffu, s, o);
            if (lane >= o) s += t2;
        }
        if (lane < NWARPS) wpre[lane] = s - u;
    }
    __syncthreads();
    if (i < NN) {
        int off = blockPre + wpre[warp] + (v - c);   // exclusive
        g_offsets[i] = off;
        g_cursor[i]  = off;
    }
}

// ---------------- scatter into CSR + precompute edge weights (packed) ----------------
__global__ void scatter_kernel() {
    int i = blockIdx.x * blockDim.x + threadIdx.x;
    if (i >= ET) return;
    int s, d;
    if (i < EE) { int2 sd = g_sd[i]; s = sd.x; d = sd.y; }
    else        { s = d = i - EE; }
    int pos = atomicAdd(&g_cursor[d], 1);
    float e = g_asrc[s] + g_adst[d];
    e = (e > 0.f) ? e : NEG_SLOPE * e;
    EW ew; ew.s = s; ew.w = __expf(e);
    g_ew[pos] = ew;                       // single STG.64
}

// ---------------- aggregate (packed weights, 4 gathers/half-warp) + ELU + fc fold ----
__global__ void aggregate_kernel(const float* __restrict__ bias,
                                 const float* __restrict__ fcw,
                                 const float* __restrict__ fcb) {
    int n    = (blockIdx.x * blockDim.x + threadIdx.x) >> 5;
    int lane = threadIdx.x & 31;
    if (n >= NN) return;
    int sub  = lane >> 4;        // 0/1: parity class of edges
    int l16  = lane & 15;        // column group

    int start = g_offsets[n];
    int end   = g_offsets[n + 1];

    float4 acc = make_float4(0.f, 0.f, 0.f, 0.f);
    float wsum = 0.f;
    int i = start + sub;
    // 4 edges in flight per half-warp (8 per warp)
    for (; i + 6 < end; i += 8) {
        EW e0 = g_ew[i];
        EW e1 = g_ew[i + 2];
        EW e2 = g_ew[i + 4];
        EW e3 = g_ew[i + 6];
        float4 h0 = *(const float4*)&g_h[(long long)e0.s * HID + l16 * 4];
        float4 h1 = *(const float4*)&g_h[(long long)e1.s * HID + l16 * 4];
        float4 h2 = *(const float4*)&g_h[(long long)e2.s * HID + l16 * 4];
        float4 h3 = *(const float4*)&g_h[(long long)e3.s * HID + l16 * 4];
        wsum += (e0.w + e1.w) + (e2.w + e3.w);
        acc.x = fmaf(e0.w, h0.x, fmaf(e1.w, h1.x, fmaf(e2.w, h2.x, fmaf(e3.w, h3.x, acc.x))));
        acc.y = fmaf(e0.w, h0.y, fmaf(e1.w, h1.y, fmaf(e2.w, h2.y, fmaf(e3.w, h3.y, acc.y))));
        acc.z = fmaf(e0.w, h0.z, fmaf(e1.w, h1.z, fmaf(e2.w, h2.z, fmaf(e3.w, h3.z, acc.z))));
        acc.w = fmaf(e0.w, h0.w, fmaf(e1.w, h1.w, fmaf(e2.w, h2.w, fmaf(e3.w, h3.w, acc.w))));
    }
    for (; i < end; i += 2) {
        EW e0 = g_ew[i];
        float4 h0 = *(const float4*)&g_h[(long long)e0.s * HID + l16 * 4];
        wsum += e0.w;
        acc.x = fmaf(e0.w, h0.x, acc.x);
        acc.y = fmaf(e0.w, h0.y, acc.y);
        acc.z = fmaf(e0.w, h0.z, acc.z);
        acc.w = fmaf(e0.w, h0.w, acc.w);
    }
    wsum += __shfl_xor_sync(0xffffffffu, wsum, 16);
    acc.x += __shfl_down_sync(0xffffffffu, acc.x, 16);
    acc.y += __shfl_down_sync(0xffffffffu, acc.y, 16);
    acc.z += __shfl_down_sync(0xffffffffu, acc.z, 16);
    acc.w += __shfl_down_sync(0xffffffffu, acc.w, 16);

    float inv = 1.0f / wsum;
    float4 b  = *(const float4*)&bias[l16 * 4];
    float o0 = acc.x * inv + b.x;
    float o1 = acc.y * inv + b.y;
    float o2 = acc.z * inv + b.z;
    float o3 = acc.w * inv + b.w;
    o0 = (o0 > 0.f) ? o0 : expm1f(o0);
    o1 = (o1 > 0.f) ? o1 : expm1f(o1);
    o2 = (o2 > 0.f) ? o2 : expm1f(o2);
    o3 = (o3 > 0.f) ? o3 : expm1f(o3);

    float4 f0 = *(const float4*)&fcw[l16 * 4];
    float4 f1 = *(const float4*)&fcw[HID + l16 * 4];
    float p0 = o0 * f0.x + o1 * f0.y + o2 * f0.z + o3 * f0.w;
    float p1 = o0 * f1.x + o1 * f1.y + o2 * f1.z + o3 * f1.w;
    #pragma unroll
    for (int o = 8; o; o >>= 1) {
        p0 += __shfl_xor_sync(0xffffffffu, p0, o);
        p1 += __shfl_xor_sync(0xffffffffu, p1, o);
    }
    if (lane == 0) {
        g_s0[n] = p0 + fcb[0];   // fold fc bias into s0
        g_s1[n] = p1;
    }
}

// ---------------- per-edge scores (4 edges per thread, packed pairs) ----------------
__global__ void score_kernel(float* __restrict__ out) {
    int t = blockIdx.x * blockDim.x + threadIdx.x;
    int e0 = t * 4;
    if (e0 >= EE) return;
    if (e0 + 4 <= EE) {
        int4 p01 = *(const int4*)&g_sd[e0];       // (s0,d0,s1,d1)
        int4 p23 = *(const int4*)&g_sd[e0 + 2];   // (s2,d2,s3,d3)
        float4 r;
        r.x = g_s0[p01.x] + g_s1[p01.y];
        r.y = g_s0[p01.z] + g_s1[p01.w];
        r.z = g_s0[p23.x] + g_s1[p23.y];
        r.w = g_s0[p23.z] + g_s1[p23.w];
        *(float4*)&out[e0] = r;
    } else {
        for (int e = e0; e < EE; e++) {
            int2 sd = g_sd[e];
            out[e] = g_s0[sd.x] + g_s1[sd.y];
        }
    }
}

// ---------------- launch: fork-join overlap of gemm with init+edge chain ----------------
extern "C" void kernel_launch(void* const* d_in, const int* in_sizes, int n_in,
                              void* d_out, int out_size) {
    const float* x   = (const float*)d_in[0];
    const void*  ei  = d_in[1];
    const float* W   = (const float*)d_in[2];
    const float* asv = (const float*)d_in[3];
    const float* adv = (const float*)d_in[4];
    const float* bias= (const float*)d_in[5];
    const float* fcw = (const float*)d_in[6];
    const float* fcb = (const float*)d_in[7];
    float* out = (float*)d_out;

    // one-time host-side stream/event setup (no device allocations)
    static cudaStream_t s2 = nullptr;
    static cudaEvent_t evFork = nullptr, evJoin = nullptr;
    if (s2 == nullptr) {
        cudaStreamCreateWithFlags(&s2, cudaStreamNonBlocking);
        cudaEventCreateWithFlags(&evFork, cudaEventDisableTiming);
        cudaEventCreateWithFlags(&evJoin, cudaEventDisableTiming);
    }

    // fork FIRST: gemm is independent of init/edges/scan
    cudaEventRecord(evFork, 0);
    cudaStreamWaitEvent(s2, evFork, 0);
    gemm_kernel<<<(NN + GR - 1) / GR, 128, 0, s2>>>(x, W, asv, adv);

    // edge branch on default stream
    init_kernel<<<(NN + 255) / 256, 256>>>((const int*)ei);
    edges_kernel<<<(EE / 2 + 255) / 256, 256>>>(ei);
    scan1_kernel<<<SCAN_G, SCAN_B>>>();
    scan3_kernel<<<SCAN_G, SCAN_B>>>();

    // join: scatter needs both gemm (asrc/adst) and scan (cursor)
    cudaEventRecord(evJoin, s2);
    cudaStreamWaitEvent(0, evJoin, 0);

    scatter_kernel<<<(ET + 255) / 256, 256>>>();
    aggregate_kernel<<<(NN * 32 + 255) / 256, 256>>>(bias, fcw, fcb);
    score_kernel<<<(EE / 4 + 255) / 256, 256>>>(out);
}

// round 13
// speedup vs baseline: 1.2094x; 1.0140x over previous
#include <cuda_runtime.h>
#include <cuda_fp16.h>
#include <math.h>

#define NN   50000
#define EE   800000
#define ET   (EE + NN)        // edges + self loops
#define FIN  128
#define HID  64
#define NEG_SLOPE 0.2f

#define SCAN_B   256
#define SCAN_G   ((NN + SCAN_B - 1) / SCAN_B)   // 196
#define NWARPS   (SCAN_B / 32)                  // 8

#define GR   128              // gemm rows per block
#define KCH  32               // gemm k-chunk per phase
#define XPAD 4                // row padding for transpose store

struct __align__(8) EW { int s; float w; };

// ---------------- scratch (device globals; no allocs allowed) ----------------
__device__ __align__(16) __half g_hh[NN * HID];  // x @ W in fp16 (sole consumer: aggregate)
__device__ float g_asrc[NN];
__device__ float g_adst[NN];
__device__ int   g_count[NN];          // degree histogram
__device__ int   g_cursor[NN];         // scatter cursors
__device__ int   g_offsets[NN + 1];    // CSR offsets
__device__ EW    g_ew[ET];             // (src, weight) per CSR slot
__device__ int2  g_sd[EE];             // packed (src,dst) int32
__device__ float g_s0[NN];
__device__ float g_s1[NN];
__device__ int   g_bsum[SCAN_G];       // per-block count sums
__device__ int   g_is64;

// packed fp32x2 helpers (Blackwell)
__device__ __forceinline__ unsigned long long fma2(unsigned long long a,
                                                   unsigned long long b,
                                                   unsigned long long c) {
    unsigned long long d;
    asm("fma.rn.f32x2 %0, %1, %2, %3;" : "=l"(d) : "l"(a), "l"(b), "l"(c));
    return d;
}
__device__ __forceinline__ unsigned long long pack2(float lo, float hi) {
    unsigned long long r;
    asm("mov.b64 %0, {%1, %2};" : "=l"(r) : "f"(lo), "f"(hi));
    return r;
}
__device__ __forceinline__ float2 unpack2(unsigned long long v) {
    float2 r;
    asm("mov.b64 {%0, %1}, %2;" : "=f"(r.x), "=f"(r.y) : "l"(v));
    return r;
}

// ---------------- init: counts=1 (self-loop pre-counted) + dtype detect ----
__global__ void init_kernel(const int* ew) {
    int i = blockIdx.x * blockDim.x + threadIdx.x;
    if (i < NN) g_count[i] = 1;          // self loop contributes 1 per node
    if (i == 0) {
        int all0 = 1;
        #pragma unroll 8
        for (int j = 0; j < 64; j++) {
            if (ew[2 * j + 1] != 0) { all0 = 0; break; }
        }
        g_is64 = all0;
    }
}

// ---------------- GEMM (f32x2) + fp16 h store + attn epilogue ----------------
__global__ void gemm_kernel(const float* __restrict__ x, const float* __restrict__ W,
                            const float* __restrict__ att_src, const float* __restrict__ att_dst) {
    __shared__ float xsT[KCH][GR + XPAD];   // [k][row]  ~16.5KB
    __shared__ float Ws[KCH][HID];          // [k][col]   8KB

    const int tid  = threadIdx.x;
    const int row0 = blockIdx.x * GR;
    const int tr   = tid >> 3;   // 0..15
    const int tc   = tid & 7;    // 0..7

    unsigned long long acc[8][4];
    #pragma unroll
    for (int i = 0; i < 8; i++)
        #pragma unroll
        for (int j = 0; j < 4; j++) acc[i][j] = 0ull;

    #pragma unroll
    for (int ph = 0; ph < FIN / KCH; ph++) {
        #pragma unroll
        for (int it = 0; it < 8; it++) {
            int f  = it * 128 + tid;
            int r  = f >> 3;
            int k4 = f & 7;
            float4 v = make_float4(0.f, 0.f, 0.f, 0.f);
            if (row0 + r < NN)
                v = *(const float4*)&x[(long long)(row0 + r) * FIN + ph * KCH + k4 * 4];
            xsT[k4 * 4 + 0][r] = v.x;
            xsT[k4 * 4 + 1][r] = v.y;
            xsT[k4 * 4 + 2][r] = v.z;
            xsT[k4 * 4 + 3][r] = v.w;
        }
        #pragma unroll
        for (int it = 0; it < 4; it++) {
            int f  = it * 128 + tid;
            int kk = f >> 4;
            int c4 = f & 15;
            *(float4*)&Ws[kk][c4 * 4] = *(const float4*)&W[(ph * KCH + kk) * HID + c4 * 4];
        }
        __syncthreads();

        #pragma unroll 4
        for (int k = 0; k < KCH; k++) {
            float4 a0 = *(const float4*)&xsT[k][tr * 8];
            float4 a1 = *(const float4*)&xsT[k][tr * 8 + 4];
            const unsigned long long* bp = (const unsigned long long*)&Ws[k][tc * 8];
            unsigned long long b0 = bp[0], b1 = bp[1], b2 = bp[2], b3 = bp[3];
            float a[8] = {a0.x, a0.y, a0.z, a0.w, a1.x, a1.y, a1.z, a1.w};
            #pragma unroll
            for (int i = 0; i < 8; i++) {
                unsigned long long ai = pack2(a[i], a[i]);
                acc[i][0] = fma2(ai, b0, acc[i][0]);
                acc[i][1] = fma2(ai, b1, acc[i][1]);
                acc[i][2] = fma2(ai, b2, acc[i][2]);
                acc[i][3] = fma2(ai, b3, acc[i][3]);
            }
        }
        __syncthreads();
    }

    float as[8], ad[8];
    #pragma unroll
    for (int j = 0; j < 8; j++) { as[j] = att_src[tc * 8 + j]; ad[j] = att_dst[tc * 8 + j]; }

    float* redA = (float*)xsT;           // [128][8]
    float* redB = redA + GR * 8;         // [128][8]

    #pragma unroll
    for (int i = 0; i < 8; i++) {
        int row = tr * 8 + i;
        int r   = row0 + row;
        float2 c0 = unpack2(acc[i][0]);
        float2 c1 = unpack2(acc[i][1]);
        float2 c2 = unpack2(acc[i][2]);
        float2 c3 = unpack2(acc[i][3]);
        if (r < NN) {
            __half2 p0 = __floats2half2_rn(c0.x, c0.y);
            __half2 p1 = __floats2half2_rn(c1.x, c1.y);
            __half2 p2 = __floats2half2_rn(c2.x, c2.y);
            __half2 p3 = __floats2half2_rn(c3.x, c3.y);
            uint4 pv;
            pv.x = *(const unsigned*)&p0;
            pv.y = *(const unsigned*)&p1;
            pv.z = *(const unsigned*)&p2;
            pv.w = *(const unsigned*)&p3;
            *(uint4*)&g_hh[(long long)r * HID + tc * 8] = pv;   // 8 cols as fp16
        }
        float pa = c0.x * as[0] + c0.y * as[1] + c1.x * as[2] + c1.y * as[3]
                 + c2.x * as[4] + c2.y * as[5] + c3.x * as[6] + c3.y * as[7];
        float pb = c0.x * ad[0] + c0.y * ad[1] + c1.x * ad[2] + c1.y * ad[3]
                 + c2.x * ad[4] + c2.y * ad[5] + c3.x * ad[6] + c3.y * ad[7];
        redA[row * 8 + tc] = pa;
        redB[row * 8 + tc] = pb;
    }
    __syncthreads();
    {
        int r = row0 + tid;
        if (r < NN) {
            float sa = 0.f, sb = 0.f;
            #pragma unroll
            for (int j = 0; j < 8; j++) { sa += redA[tid * 8 + j]; sb += redB[tid * 8 + j]; }
            g_asrc[r] = sa;
            g_adst[r] = sb;
        }
    }
}

// ---------------- edges: packed conversion + dst histogram (2 edges/thread) ----
__global__ void edges_kernel(const void* ei) {
    int t  = blockIdx.x * blockDim.x + threadIdx.x;
    int i0 = t * 2;
    if (i0 >= EE) return;
    int is64 = g_is64;
    int s0, d0, s1, d1;
    if (is64) {
        longlong2 sv = *(const longlong2*)((const long long*)ei + i0);
        longlong2 dv = *(const longlong2*)((const long long*)ei + EE + i0);
        s0 = (int)sv.x; s1 = (int)sv.y;
        d0 = (int)dv.x; d1 = (int)dv.y;
    } else {
        int2 sv = *(const int2*)((const int*)ei + i0);
        int2 dv = *(const int2*)((const int*)ei + EE + i0);
        s0 = sv.x; s1 = sv.y;
        d0 = dv.x; d1 = dv.y;
    }
    g_sd[i0] = make_int2(s0, d0);
    atomicAdd(&g_count[d0], 1);
    if (i0 + 1 < EE) {
        g_sd[i0 + 1] = make_int2(s1, d1);
        atomicAdd(&g_count[d1], 1);
    }
}

// ---------------- scan phase 1 (block sums) ----------------
__global__ void scan1_kernel() {
    __shared__ int wsum[NWARPS];
    int i = blockIdx.x * SCAN_B + threadIdx.x;
    int lane = threadIdx.x & 31;
    int warp = threadIdx.x >> 5;
    int c = (i < NN) ? g_count[i] : 0;
    int v = c;
    #pragma unroll
    for (int o = 16; o; o >>= 1) v += __shfl_xor_sync(0xffffffffu, v, o);
    if (lane == 0) wsum[warp] = v;
    __syncthreads();
    if (threadIdx.x == 0) {
        int s = 0;
        #pragma unroll
        for (int w = 0; w < NWARPS; w++) s += wsum[w];
        g_bsum[blockIdx.x] = s;
    }
}

// ---------------- scan phase 2: downsweep with redundant block-sum scan ----
__global__ void scan3_kernel() {
    __shared__ int wpre[NWARPS];
    __shared__ int bsc[SCAN_B];
    int t = threadIdx.x;
    int bv = (t < SCAN_G) ? g_bsum[t] : 0;
    bsc[t] = bv;
    __syncthreads();
    for (int off = 1; off < SCAN_B; off <<= 1) {
        int add = (t >= off) ? bsc[t - off] : 0;
        __syncthreads();
        bsc[t] += add;
        __syncthreads();
    }
    int blockPre = (blockIdx.x == 0) ? 0 : bsc[blockIdx.x - 1];
    if (blockIdx.x == 0 && t == 0) g_offsets[NN] = ET;

    int i = blockIdx.x * SCAN_B + t;
    int lane = t & 31;
    int warp = t >> 5;
    int c = (i < NN) ? g_count[i] : 0;
    int v = c;
    #pragma unroll
    for (int o = 1; o < 32; o <<= 1) {
        int u = __shfl_up_sync(0xffffffffu, v, o);
        if (lane >= o) v += u;
    }
    if (lane == 31) wpre[warp] = v;
    __syncthreads();
    if (warp == 0) {
        int u = (lane < NWARPS) ? wpre[lane] : 0;
        int s = u;
        #pragma unroll
        for (int o = 1; o < 32; o <<= 1) {
            int t2 = __shfl_up_sync(0xffffffffu, s, o);
            if (lane >= o) s += t2;
        }
        if (lane < NWARPS) wpre[lane] = s - u;
    }
    __syncthreads();
    if (i < NN) {
        int off = blockPre + wpre[warp] + (v - c);   // exclusive
        g_offsets[i] = off;
        g_cursor[i]  = off;
    }
}

// ---------------- scatter into CSR + precompute edge weights (packed) ----------------
__global__ void scatter_kernel() {
    int i = blockIdx.x * blockDim.x + threadIdx.x;
    if (i >= ET) return;
    int s, d;
    if (i < EE) { int2 sd = g_sd[i]; s = sd.x; d = sd.y; }
    else        { s = d = i - EE; }
    int pos = atomicAdd(&g_cursor[d], 1);
    float e = g_asrc[s] + g_adst[d];
    e = (e > 0.f) ? e : NEG_SLOPE * e;
    EW ew; ew.s = s; ew.w = __expf(e);
    g_ew[pos] = ew;                       // single STG.64
}

// ---------------- aggregate (fp16 h gathers) + ELU + fc fold ----------------
__global__ void aggregate_kernel(const float* __restrict__ bias,
                                 const float* __restrict__ fcw,
                                 const float* __restrict__ fcb) {
    int n    = (blockIdx.x * blockDim.x + threadIdx.x) >> 5;
    int lane = threadIdx.x & 31;
    if (n >= NN) return;
    int sub  = lane >> 4;        // 0/1: parity class of edges
    int l16  = lane & 15;        // column group (4 cols each)

    int start = g_offsets[n];
    int end   = g_offsets[n + 1];

    float4 acc = make_float4(0.f, 0.f, 0.f, 0.f);
    float wsum = 0.f;
    int i = start + sub;
    // 4 edges in flight per half-warp (8 per warp); 8B fp16 gathers
    for (; i + 6 < end; i += 8) {
        EW e0 = g_ew[i];
        EW e1 = g_ew[i + 2];
        EW e2 = g_ew[i + 4];
        EW e3 = g_ew[i + 6];
        uint2 r0 = *(const uint2*)&g_hh[(long long)e0.s * HID + l16 * 4];
        uint2 r1 = *(const uint2*)&g_hh[(long long)e1.s * HID + l16 * 4];
        uint2 r2 = *(const uint2*)&g_hh[(long long)e2.s * HID + l16 * 4];
        uint2 r3 = *(const uint2*)&g_hh[(long long)e3.s * HID + l16 * 4];
        wsum += (e0.w + e1.w) + (e2.w + e3.w);
        float2 f0a = __half22float2(*(const __half2*)&r0.x);
        float2 f0b = __half22float2(*(const __half2*)&r0.y);
        float2 f1a = __half22float2(*(const __half2*)&r1.x);
        float2 f1b = __half22float2(*(const __half2*)&r1.y);
        float2 f2a = __half22float2(*(const __half2*)&r2.x);
        float2 f2b = __half22float2(*(const __half2*)&r2.y);
        float2 f3a = __half22float2(*(const __half2*)&r3.x);
        float2 f3b = __half22float2(*(const __half2*)&r3.y);
        acc.x = fmaf(e0.w, f0a.x, fmaf(e1.w, f1a.x, fmaf(e2.w, f2a.x, fmaf(e3.w, f3a.x, acc.x))));
        acc.y = fmaf(e0.w, f0a.y, fmaf(e1.w, f1a.y, fmaf(e2.w, f2a.y, fmaf(e3.w, f3a.y, acc.y))));
        acc.z = fmaf(e0.w, f0b.x, fmaf(e1.w, f1b.x, fmaf(e2.w, f2b.x, fmaf(e3.w, f3b.x, acc.z))));
        acc.w = fmaf(e0.w, f0b.y, fmaf(e1.w, f1b.y, fmaf(e2.w, f2b.y, fmaf(e3.w, f3b.y, acc.w))));
    }
    for (; i < end; i += 2) {
        EW e0 = g_ew[i];
        uint2 r0 = *(const uint2*)&g_hh[(long long)e0.s * HID + l16 * 4];
        float2 f0a = __half22float2(*(const __half2*)&r0.x);
        float2 f0b = __half22float2(*(const __half2*)&r0.y);
        wsum += e0.w;
        acc.x = fmaf(e0.w, f0a.x, acc.x);
        acc.y = fmaf(e0.w, f0a.y, acc.y);
        acc.z = fmaf(e0.w, f0b.x, acc.z);
        acc.w = fmaf(e0.w, f0b.y, acc.w);
    }
    wsum += __shfl_xor_sync(0xffffffffu, wsum, 16);
    acc.x += __shfl_down_sync(0xffffffffu, acc.x, 16);
    acc.y += __shfl_down_sync(0xffffffffu, acc.y, 16);
    acc.z += __shfl_down_sync(0xffffffffu, acc.z, 16);
    acc.w += __shfl_down_sync(0xffffffffu, acc.w, 16);

    float inv = 1.0f / wsum;
    float4 b  = *(const float4*)&bias[l16 * 4];
    float o0 = acc.x * inv + b.x;
    float o1 = acc.y * inv + b.y;
    float o2 = acc.z * inv + b.z;
    float o3 = acc.w * inv + b.w;
    o0 = (o0 > 0.f) ? o0 : expm1f(o0);
    o1 = (o1 > 0.f) ? o1 : expm1f(o1);
    o2 = (o2 > 0.f) ? o2 : expm1f(o2);
    o3 = (o3 > 0.f) ? o3 : expm1f(o3);

    float4 f0 = *(const float4*)&fcw[l16 * 4];
    float4 f1 = *(const float4*)&fcw[HID + l16 * 4];
    float p0 = o0 * f0.x + o1 * f0.y + o2 * f0.z + o3 * f0.w;
    float p1 = o0 * f1.x + o1 * f1.y + o2 * f1.z + o3 * f1.w;
    #pragma unroll
    for (int o = 8; o; o >>= 1) {
        p0 += __shfl_xor_sync(0xffffffffu, p0, o);
        p1 += __shfl_xor_sync(0xffffffffu, p1, o);
    }
    if (lane == 0) {
        g_s0[n] = p0 + fcb[0];   // fold fc bias into s0
        g_s1[n] = p1;
    }
}

// ---------------- per-edge scores (4 edges per thread, packed pairs) ----------------
__global__ void score_kernel(float* __restrict__ out) {
    int t = blockIdx.x * blockDim.x + threadIdx.x;
    int e0 = t * 4;
    if (e0 >= EE) return;
    if (e0 + 4 <= EE) {
        int4 p01 = *(const int4*)&g_sd[e0];       // (s0,d0,s1,d1)
        int4 p23 = *(const int4*)&g_sd[e0 + 2];   // (s2,d2,s3,d3)
        float4 r;
        r.x = g_s0[p01.x] + g_s1[p01.y];
        r.y = g_s0[p01.z] + g_s1[p01.w];
        r.z = g_s0[p23.x] + g_s1[p23.y];
        r.w = g_s0[p23.z] + g_s1[p23.w];
        *(float4*)&out[e0] = r;
    } else {
        for (int e = e0; e < EE; e++) {
            int2 sd = g_sd[e];
            out[e] = g_s0[sd.x] + g_s1[sd.y];
        }
    }
}

// ---------------- launch: fork-join overlap of gemm with init+edge chain ----------------
extern "C" void kernel_launch(void* const* d_in, const int* in_sizes, int n_in,
                              void* d_out, int out_size) {
    const float* x   = (const float*)d_in[0];
    const void*  ei  = d_in[1];
    const float* W   = (const float*)d_in[2];
    const float* asv = (const float*)d_in[3];
    const float* adv = (const float*)d_in[4];
    const float* bias= (const float*)d_in[5];
    const float* fcw = (const float*)d_in[6];
    const float* fcb = (const float*)d_in[7];
    float* out = (float*)d_out;

    // one-time host-side stream/event setup (no device allocations)
    static cudaStream_t s2 = nullptr;
    static cudaEvent_t evFork = nullptr, evJoin = nullptr;
    if (s2 == nullptr) {
        cudaStreamCreateWithFlags(&s2, cudaStreamNonBlocking);
        cudaEventCreateWithFlags(&evFork, cudaEventDisableTiming);
        cudaEventCreateWithFlags(&evJoin, cudaEventDisableTiming);
    }

    // fork FIRST: gemm is independent of init/edges/scan
    cudaEventRecord(evFork, 0);
    cudaStreamWaitEvent(s2, evFork, 0);
    gemm_kernel<<<(NN + GR - 1) / GR, 128, 0, s2>>>(x, W, asv, adv);

    // edge branch on default stream
    init_kernel<<<(NN + 255) / 256, 256>>>((const int*)ei);
    edges_kernel<<<(EE / 2 + 255) / 256, 256>>>(ei);
    scan1_kernel<<<SCAN_G, SCAN_B>>>();
    scan3_kernel<<<SCAN_G, SCAN_B>>>();

    // join: scatter needs both gemm (asrc/adst) and scan (cursor)
    cudaEventRecord(evJoin, s2);
    cudaStreamWaitEvent(0, evJoin, 0);

    scatter_kernel<<<(ET + 255) / 256, 256>>>();
    aggregate_kernel<<<(NN * 32 + 255) / 256, 256>>>(bias, fcw, fcb);
    score_kernel<<<(EE / 4 + 255) / 256, 256>>>(out);
}

// round 14
// speedup vs baseline: 1.2209x; 1.0095x over previous
#include <cuda_runtime.h>
#include <cuda_fp16.h>
#include <math.h>

#define NN   50000
#define EE   800000
#define ET   (EE + NN)        // edges + self loops
#define FIN  128
#define HID  64
#define NEG_SLOPE 0.2f

#define SCAN_B   256
#define SCAN_G   ((NN + SCAN_B - 1) / SCAN_B)   // 196
#define NWARPS   (SCAN_B / 32)                  // 8

#define GR   128              // gemm rows per block
#define KCH  32               // gemm k-chunk per phase
#define XPAD 4                // row padding for transpose store

struct __align__(8) EW { int s; float w; };

// ---------------- scratch (device globals; no allocs allowed) ----------------
__device__ __align__(16) __half g_hh[NN * HID];  // x @ W in fp16 (sole consumer: aggregate)
__device__ float g_asrc[NN];
__device__ float g_adst[NN];
__device__ int   g_count[NN];          // degree histogram (zero at entry; restored by aggregate)
__device__ int   g_cursor[NN];         // scatter cursors
__device__ int   g_offsets[NN + 1];    // CSR offsets
__device__ EW    g_ew[ET];             // (src, weight) per CSR slot
__device__ int2  g_sd[EE];             // packed (src,dst) int32
__device__ float g_s0[NN];
__device__ float g_s1[NN];
__device__ int   g_bsum[SCAN_G];       // per-block count sums
__device__ int   g_barrier;            // scan spin barrier (reset by edges each launch)

// packed fp32x2 helpers (Blackwell)
__device__ __forceinline__ unsigned long long fma2(unsigned long long a,
                                                   unsigned long long b,
                                                   unsigned long long c) {
    unsigned long long d;
    asm("fma.rn.f32x2 %0, %1, %2, %3;" : "=l"(d) : "l"(a), "l"(b), "l"(c));
    return d;
}
__device__ __forceinline__ unsigned long long pack2(float lo, float hi) {
    unsigned long long r;
    asm("mov.b64 %0, {%1, %2};" : "=l"(r) : "f"(lo), "f"(hi));
    return r;
}
__device__ __forceinline__ float2 unpack2(unsigned long long v) {
    float2 r;
    asm("mov.b64 {%0, %1}, %2;" : "=f"(r.x), "=f"(r.y) : "l"(v));
    return r;
}

// ---------------- GEMM (f32x2) + fp16 h store + attn epilogue ----------------
__global__ void gemm_kernel(const float* __restrict__ x, const float* __restrict__ W,
                            const float* __restrict__ att_src, const float* __restrict__ att_dst) {
    __shared__ float xsT[KCH][GR + XPAD];   // [k][row]  ~16.5KB
    __shared__ float Ws[KCH][HID];          // [k][col]   8KB

    const int tid  = threadIdx.x;
    const int row0 = blockIdx.x * GR;
    const int tr   = tid >> 3;   // 0..15
    const int tc   = tid & 7;    // 0..7

    unsigned long long acc[8][4];
    #pragma unroll
    for (int i = 0; i < 8; i++)
        #pragma unroll
        for (int j = 0; j < 4; j++) acc[i][j] = 0ull;

    #pragma unroll
    for (int ph = 0; ph < FIN / KCH; ph++) {
        #pragma unroll
        for (int it = 0; it < 8; it++) {
            int f  = it * 128 + tid;
            int r  = f >> 3;
            int k4 = f & 7;
            float4 v = make_float4(0.f, 0.f, 0.f, 0.f);
            if (row0 + r < NN)
                v = *(const float4*)&x[(long long)(row0 + r) * FIN + ph * KCH + k4 * 4];
            xsT[k4 * 4 + 0][r] = v.x;
            xsT[k4 * 4 + 1][r] = v.y;
            xsT[k4 * 4 + 2][r] = v.z;
            xsT[k4 * 4 + 3][r] = v.w;
        }
        #pragma unroll
        for (int it = 0; it < 4; it++) {
            int f  = it * 128 + tid;
            int kk = f >> 4;
            int c4 = f & 15;
            *(float4*)&Ws[kk][c4 * 4] = *(const float4*)&W[(ph * KCH + kk) * HID + c4 * 4];
        }
        __syncthreads();

        #pragma unroll 4
        for (int k = 0; k < KCH; k++) {
            float4 a0 = *(const float4*)&xsT[k][tr * 8];
            float4 a1 = *(const float4*)&xsT[k][tr * 8 + 4];
            const unsigned long long* bp = (const unsigned long long*)&Ws[k][tc * 8];
            unsigned long long b0 = bp[0], b1 = bp[1], b2 = bp[2], b3 = bp[3];
            float a[8] = {a0.x, a0.y, a0.z, a0.w, a1.x, a1.y, a1.z, a1.w};
            #pragma unroll
            for (int i = 0; i < 8; i++) {
                unsigned long long ai = pack2(a[i], a[i]);
                acc[i][0] = fma2(ai, b0, acc[i][0]);
                acc[i][1] = fma2(ai, b1, acc[i][1]);
                acc[i][2] = fma2(ai, b2, acc[i][2]);
                acc[i][3] = fma2(ai, b3, acc[i][3]);
            }
        }
        __syncthreads();
    }

    float as[8], ad[8];
    #pragma unroll
    for (int j = 0; j < 8; j++) { as[j] = att_src[tc * 8 + j]; ad[j] = att_dst[tc * 8 + j]; }

    float* redA = (float*)xsT;           // [128][8]
    float* redB = redA + GR * 8;         // [128][8]

    #pragma unroll
    for (int i = 0; i < 8; i++) {
        int row = tr * 8 + i;
        int r   = row0 + row;
        float2 c0 = unpack2(acc[i][0]);
        float2 c1 = unpack2(acc[i][1]);
        float2 c2 = unpack2(acc[i][2]);
        float2 c3 = unpack2(acc[i][3]);
        if (r < NN) {
            __half2 p0 = __floats2half2_rn(c0.x, c0.y);
            __half2 p1 = __floats2half2_rn(c1.x, c1.y);
            __half2 p2 = __floats2half2_rn(c2.x, c2.y);
            __half2 p3 = __floats2half2_rn(c3.x, c3.y);
            uint4 pv;
            pv.x = *(const unsigned*)&p0;
            pv.y = *(const unsigned*)&p1;
            pv.z = *(const unsigned*)&p2;
            pv.w = *(const unsigned*)&p3;
            *(uint4*)&g_hh[(long long)r * HID + tc * 8] = pv;   // 8 cols as fp16
        }
        float pa = c0.x * as[0] + c0.y * as[1] + c1.x * as[2] + c1.y * as[3]
                 + c2.x * as[4] + c2.y * as[5] + c3.x * as[6] + c3.y * as[7];
        float pb = c0.x * ad[0] + c0.y * ad[1] + c1.x * ad[2] + c1.y * ad[3]
                 + c2.x * ad[4] + c2.y * ad[5] + c3.x * ad[6] + c3.y * ad[7];
        redA[row * 8 + tc] = pa;
        redB[row * 8 + tc] = pb;
    }
    __syncthreads();
    {
        int r = row0 + tid;
        if (r < NN) {
            float sa = 0.f, sb = 0.f;
            #pragma unroll
            for (int j = 0; j < 8; j++) { sa += redA[tid * 8 + j]; sb += redB[tid * 8 + j]; }
            g_asrc[r] = sa;
            g_adst[r] = sb;
        }
    }
}

// ---------------- edges: detect + packed conversion + dst histogram (2 edges/thread) ----
// Also resets the scan spin barrier (global thread 0).
__global__ void edges_kernel(const void* ei) {
    __shared__ int sIs64;
    int t  = blockIdx.x * blockDim.x + threadIdx.x;
    if (threadIdx.x == 0) {
        if (blockIdx.x == 0) g_barrier = 0;      // reset for this launch's scan
        const int* ew = (const int*)ei;
        int all0 = 1;
        #pragma unroll 8
        for (int j = 0; j < 64; j++) {
            if (ew[2 * j + 1] != 0) { all0 = 0; break; }
        }
        sIs64 = all0;
    }
    __syncthreads();
    int is64 = sIs64;

    int i0 = t * 2;
    if (i0 >= EE) return;
    int s0, d0, s1, d1;
    if (is64) {
        longlong2 sv = *(const longlong2*)((const long long*)ei + i0);
        longlong2 dv = *(const longlong2*)((const long long*)ei + EE + i0);
        s0 = (int)sv.x; s1 = (int)sv.y;
        d0 = (int)dv.x; d1 = (int)dv.y;
    } else {
        int2 sv = *(const int2*)((const int*)ei + i0);
        int2 dv = *(const int2*)((const int*)ei + EE + i0);
        s0 = sv.x; s1 = sv.y;
        d0 = dv.x; d1 = dv.y;
    }
    g_sd[i0] = make_int2(s0, d0);
    atomicAdd(&g_count[d0], 1);
    if (i0 + 1 < EE) {
        g_sd[i0 + 1] = make_int2(s1, d1);
        atomicAdd(&g_count[d1], 1);
    }
}

// ---------------- single-kernel scan with global spin barrier ----------------
// 196 blocks, all resident in wave 1 (256 thr, ~1.1KB smem) -> spin is safe.
__global__ void scan_kernel() {
    __shared__ int wsum[NWARPS];   // inclusive warp totals
    __shared__ int wpre[NWARPS];   // exclusive warp prefixes
    __shared__ int sTot;           // block total
    __shared__ int bsc[SCAN_B];    // block-sum scan

    int t    = threadIdx.x;
    int bid  = blockIdx.x;
    int i    = bid * SCAN_B + t;
    int lane = t & 31;
    int warp = t >> 5;

    // counts are zero-based; +1 is the self loop
    int c = (i < NN) ? g_count[i] + 1 : 0;
    int v = c;
    #pragma unroll
    for (int o = 1; o < 32; o <<= 1) {
        int u = __shfl_up_sync(0xffffffffu, v, o);
        if (lane >= o) v += u;
    }
    if (lane == 31) wsum[warp] = v;
    __syncthreads();
    if (warp == 0) {
        int u = (lane < NWARPS) ? wsum[lane] : 0;
        int s = u;
        #pragma unroll
        for (int o = 1; o < 32; o <<= 1) {
            int t2 = __shfl_up_sync(0xffffffffu, s, o);
            if (lane >= o) s += t2;
        }
        if (lane < NWARPS) wpre[lane] = s - u;
        if (lane == NWARPS - 1) sTot = s;
    }
    __syncthreads();

    // publish block sum; global barrier (thread 0 spins, block released by bar)
    if (t == 0) {
        g_bsum[bid] = sTot;
        __threadfence();
        atomicAdd(&g_barrier, 1);
        while (atomicAdd(&g_barrier, 0) < SCAN_G) { }
        __threadfence();
    }
    __syncthreads();

    // scan the 196 block sums (redundantly per block, cheap)
    int bv = (t < SCAN_G) ? g_bsum[t] : 0;
    bsc[t] = bv;
    __syncthreads();
    for (int off = 1; off < SCAN_B; off <<= 1) {
        int add = (t >= off) ? bsc[t - off] : 0;
        __syncthreads();
        bsc[t] += add;
        __syncthreads();
    }
    int blockPre = (bid == 0) ? 0 : bsc[bid - 1];
    if (bid == 0 && t == 0) g_offsets[NN] = ET;

    if (i < NN) {
        int off = blockPre + wpre[warp] + (v - c);   // exclusive
        g_offsets[i] = off;
        g_cursor[i]  = off;
    }
}

// ---------------- scatter into CSR + precompute edge weights (packed) ----------------
__global__ void scatter_kernel() {
    int i = blockIdx.x * blockDim.x + threadIdx.x;
    if (i >= ET) return;
    int s, d;
    if (i < EE) { int2 sd = g_sd[i]; s = sd.x; d = sd.y; }
    else        { s = d = i - EE; }
    int pos = atomicAdd(&g_cursor[d], 1);
    float e = g_asrc[s] + g_adst[d];
    e = (e > 0.f) ? e : NEG_SLOPE * e;
    EW ew; ew.s = s; ew.w = __expf(e);
    g_ew[pos] = ew;                       // single STG.64
}

// ---------------- aggregate (fp16 h gathers) + ELU + fc fold + count reset ----
__global__ void aggregate_kernel(const float* __restrict__ bias,
                                 const float* __restrict__ fcw,
                                 const float* __restrict__ fcb) {
    int n    = (blockIdx.x * blockDim.x + threadIdx.x) >> 5;
    int lane = threadIdx.x & 31;
    if (n >= NN) return;
    int sub  = lane >> 4;        // 0/1: parity class of edges
    int l16  = lane & 15;        // column group (4 cols each)

    int start = g_offsets[n];
    int end   = g_offsets[n + 1];

    float4 acc = make_float4(0.f, 0.f, 0.f, 0.f);
    float wsum = 0.f;
    int i = start + sub;
    for (; i + 6 < end; i += 8) {
        EW e0 = g_ew[i];
        EW e1 = g_ew[i + 2];
        EW e2 = g_ew[i + 4];
        EW e3 = g_ew[i + 6];
        uint2 r0 = *(const uint2*)&g_hh[(long long)e0.s * HID + l16 * 4];
        uint2 r1 = *(const uint2*)&g_hh[(long long)e1.s * HID + l16 * 4];
        uint2 r2 = *(const uint2*)&g_hh[(long long)e2.s * HID + l16 * 4];
        uint2 r3 = *(const uint2*)&g_hh[(long long)e3.s * HID + l16 * 4];
        wsum += (e0.w + e1.w) + (e2.w + e3.w);
        float2 f0a = __half22float2(*(const __half2*)&r0.x);
        float2 f0b = __half22float2(*(const __half2*)&r0.y);
        float2 f1a = __half22float2(*(const __half2*)&r1.x);
        float2 f1b = __half22float2(*(const __half2*)&r1.y);
        float2 f2a = __half22float2(*(const __half2*)&r2.x);
        float2 f2b = __half22float2(*(const __half2*)&r2.y);
        float2 f3a = __half22float2(*(const __half2*)&r3.x);
        float2 f3b = __half22float2(*(const __half2*)&r3.y);
        acc.x = fmaf(e0.w, f0a.x, fmaf(e1.w, f1a.x, fmaf(e2.w, f2a.x, fmaf(e3.w, f3a.x, acc.x))));
        acc.y = fmaf(e0.w, f0a.y, fmaf(e1.w, f1a.y, fmaf(e2.w, f2a.y, fmaf(e3.w, f3a.y, acc.y))));
        acc.z = fmaf(e0.w, f0b.x, fmaf(e1.w, f1b.x, fmaf(e2.w, f2b.x, fmaf(e3.w, f3b.x, acc.z))));
        acc.w = fmaf(e0.w, f0b.y, fmaf(e1.w, f1b.y, fmaf(e2.w, f2b.y, fmaf(e3.w, f3b.y, acc.w))));
    }
    for (; i < end; i += 2) {
        EW e0 = g_ew[i];
        uint2 r0 = *(const uint2*)&g_hh[(long long)e0.s * HID + l16 * 4];
        float2 f0a = __half22float2(*(const __half2*)&r0.x);
        float2 f0b = __half22float2(*(const __half2*)&r0.y);
        wsum += e0.w;
        acc.x = fmaf(e0.w, f0a.x, acc.x);
        acc.y = fmaf(e0.w, f0a.y, acc.y);
        acc.z = fmaf(e0.w, f0b.x, acc.z);
        acc.w = fmaf(e0.w, f0b.y, acc.w);
    }
    wsum += __shfl_xor_sync(0xffffffffu, wsum, 16);
    acc.x += __shfl_down_sync(0xffffffffu, acc.x, 16);
    acc.y += __shfl_down_sync(0xffffffffu, acc.y, 16);
    acc.z += __shfl_down_sync(0xffffffffu, acc.z, 16);
    acc.w += __shfl_down_sync(0xffffffffu, acc.w, 16);

    float inv = 1.0f / wsum;
    float4 b  = *(const float4*)&bias[l16 * 4];
    float o0 = acc.x * inv + b.x;
    float o1 = acc.y * inv + b.y;
    float o2 = acc.z * inv + b.z;
    float o3 = acc.w * inv + b.w;
    o0 = (o0 > 0.f) ? o0 : expm1f(o0);
    o1 = (o1 > 0.f) ? o1 : expm1f(o1);
    o2 = (o2 > 0.f) ? o2 : expm1f(o2);
    o3 = (o3 > 0.f) ? o3 : expm1f(o3);

    float4 f0 = *(const float4*)&fcw[l16 * 4];
    float4 f1 = *(const float4*)&fcw[HID + l16 * 4];
    float p0 = o0 * f0.x + o1 * f0.y + o2 * f0.z + o3 * f0.w;
    float p1 = o0 * f1.x + o1 * f1.y + o2 * f1.z + o3 * f1.w;
    #pragma unroll
    for (int o = 8; o; o >>= 1) {
        p0 += __shfl_xor_sync(0xffffffffu, p0, o);
        p1 += __shfl_xor_sync(0xffffffffu, p1, o);
    }
    if (lane == 0) {
        g_s0[n] = p0 + fcb[0];   // fold fc bias into s0
        g_s1[n] = p1;
        g_count[n] = 0;          // restore zero-count invariant for next launch
    }
}

// ---------------- per-edge scores (4 edges per thread, packed pairs) ----------------
__global__ void score_kernel(float* __restrict__ out) {
    int t = blockIdx.x * blockDim.x + threadIdx.x;
    int e0 = t * 4;
    if (e0 >= EE) return;
    if (e0 + 4 <= EE) {
        int4 p01 = *(const int4*)&g_sd[e0];       // (s0,d0,s1,d1)
        int4 p23 = *(const int4*)&g_sd[e0 + 2];   // (s2,d2,s3,d3)
        float4 r;
        r.x = g_s0[p01.x] + g_s1[p01.y];
        r.y = g_s0[p01.z] + g_s1[p01.w];
        r.z = g_s0[p23.x] + g_s1[p23.y];
        r.w = g_s0[p23.z] + g_s1[p23.w];
        *(float4*)&out[e0] = r;
    } else {
        for (int e = e0; e < EE; e++) {
            int2 sd = g_sd[e];
            out[e] = g_s0[sd.x] + g_s1[sd.y];
        }
    }
}

// ---------------- launch: fork-join overlap of gemm with edge chain ----------------
extern "C" void kernel_launch(void* const* d_in, const int* in_sizes, int n_in,
                              void* d_out, int out_size) {
    const float* x   = (const float*)d_in[0];
    const void*  ei  = d_in[1];
    const float* W   = (const float*)d_in[2];
    const float* asv = (const float*)d_in[3];
    const float* adv = (const float*)d_in[4];
    const float* bias= (const float*)d_in[5];
    const float* fcw = (const float*)d_in[6];
    const float* fcb = (const float*)d_in[7];
    float* out = (float*)d_out;

    // one-time host-side stream/event setup (no device allocations)
    static cudaStream_t s2 = nullptr;
    static cudaEvent_t evFork = nullptr, evJoin = nullptr;
    if (s2 == nullptr) {
        cudaStreamCreateWithFlags(&s2, cudaStreamNonBlocking);
        cudaEventCreateWithFlags(&evFork, cudaEventDisableTiming);
        cudaEventCreateWithFlags(&evJoin, cudaEventDisableTiming);
    }

    // fork: gemm is independent of edges/scan
    cudaEventRecord(evFork, 0);
    cudaStreamWaitEvent(s2, evFork, 0);
    gemm_kernel<<<(NN + GR - 1) / GR, 128, 0, s2>>>(x, W, asv, adv);

    // edge branch on default stream
    edges_kernel<<<(EE / 2 + 255) / 256, 256>>>(ei);
    scan_kernel<<<SCAN_G, SCAN_B>>>();

    // join: scatter needs both gemm (asrc/adst) and scan (cursor)
    cudaEventRecord(evJoin, s2);
    cudaStreamWaitEvent(0, evJoin, 0);

    scatter_kernel<<<(ET + 255) / 256, 256>>>();
    aggregate_kernel<<<(NN * 32 + 255) / 256, 256>>>(bias, fcw, fcb);
    score_kernel<<<(EE / 4 + 255) / 256, 256>>>(out);
}